// round 5
// baseline (speedup 1.0000x reference)
#include <cuda_runtime.h>
#include <cuda_bf16.h>
#include <math_constants.h>

// Shapes (fixed for this problem)
#define B  32
#define S  4096
#define H  1024
#define D  2048   // 2*H

#define HS 16           // h-splits for vpart
#define HC (H / HS)     // 64 h per split

#define NTILE   (B * S / 64)   // 2048 s-tiles of 64 rows
#define NCTA_E  456            // 152 SMs * 3 CTAs, persistent

// Scratch (device globals; no allocation allowed)
__device__ float g_vpart[HS][B * D];  // h-split partials of v = W^T hidden
__device__ float g_v[B * D];
__device__ float g_energy[B * S];
__device__ unsigned int g_ticket;     // dynamic work-stealing counter

// ---------------------------------------------------------------------------
// Kernel 0: reset the ticket (graph-capturable, deterministic)
// ---------------------------------------------------------------------------
__global__ void k_reset() { g_ticket = 0u; }

// ---------------------------------------------------------------------------
// Kernel 1: v_part[hs][b][d] = sum_{h in chunk hs} hidden[b][h] * W[h][d]
// grid (D/128, B/8, HS) = 1024 CTAs, block 128.
// ---------------------------------------------------------------------------
__global__ __launch_bounds__(128) void k_vpart(const float* __restrict__ hidden,
                                               const float* __restrict__ W) {
    const int tid = threadIdx.x;
    const int d   = blockIdx.x * 128 + tid;
    const int bg  = blockIdx.y;           // batch group of 8
    const int hs  = blockIdx.z;           // h chunk of HC

    __shared__ float hsm[8][HC];
    for (int idx = tid; idx < 8 * HC; idx += 128) {
        int bl = idx / HC, hl = idx % HC;
        hsm[bl][hl] = hidden[(bg * 8 + bl) * H + hs * HC + hl];
    }
    __syncthreads();

    float acc[8];
#pragma unroll
    for (int j = 0; j < 8; ++j) acc[j] = 0.f;

    const float* Wp = W + (size_t)(hs * HC) * D + d;
#pragma unroll 16
    for (int hl = 0; hl < HC; ++hl) {
        float w = Wp[(size_t)hl * D];
#pragma unroll
        for (int j = 0; j < 8; ++j) acc[j] += hsm[j][hl] * w;
    }

#pragma unroll
    for (int j = 0; j < 8; ++j)
        g_vpart[hs][(bg * 8 + j) * D + d] = acc[j];
}

// ---------------------------------------------------------------------------
// Kernel 1b: v = sum of HS partials (deterministic, no atomics)
// ---------------------------------------------------------------------------
__global__ void k_vreduce() {
    int idx = blockIdx.x * blockDim.x + threadIdx.x;   // B*D threads
    if (idx < B * D) {
        float s = 0.f;
#pragma unroll
        for (int p = 0; p < HS; ++p) s += g_vpart[p][idx];
        g_v[idx] = s;
    }
}

// ---------------------------------------------------------------------------
// Kernel 2: energies[b][s] = dot(enc[b][s][:], v[b][:])
// Persistent 456 CTAs with DYNAMIC work stealing (atomic ticket): keeps the
// no-wave-transition benefit while letting fast CTAs absorb the ~2x
// cross-CTA L1tex-queue spread that sank the static-partition version.
// Output position depends only on the tile id -> deterministic.
// ---------------------------------------------------------------------------
__global__ __launch_bounds__(512, 3) void k_energy(const float* __restrict__ enc) {
    const int tid  = threadIdx.x;
    const int warp = tid >> 5;
    const int lane = tid & 31;

    __shared__ float4 vsm[D / 4];   // 8KB
    __shared__ int s_tile;

    for (;;) {
        if (tid == 0) s_tile = (int)atomicAdd(&g_ticket, 1u);
        __syncthreads();              // publish s_tile, drain old vsm readers
        const int t = s_tile;
        if (t >= NTILE) break;

        const int b  = t >> 6;        // 64 tiles per batch
        const int st = (t & 63) * 64; // s offset within batch

        vsm[tid] = reinterpret_cast<const float4*>(g_v + b * D)[tid];
        __syncthreads();

        const int s0 = st + warp * 4;
#pragma unroll
        for (int r = 0; r < 4; ++r) {
            const int s = s0 + r;
            const float4* e4 = reinterpret_cast<const float4*>(
                enc + ((size_t)b * S + s) * D);
            float acc = 0.f;
#pragma unroll
            for (int i = 0; i < 16; ++i) {
                float4 e = __ldcs(&e4[i * 32 + lane]);
                float4 v = vsm[i * 32 + lane];
                acc += e.x * v.x + e.y * v.y + e.z * v.z + e.w * v.w;
            }
#pragma unroll
            for (int off = 16; off > 0; off >>= 1)
                acc += __shfl_xor_sync(0xFFFFFFFFu, acc, off);
            if (lane == 0) g_energy[b * S + s] = acc;
        }
        __syncthreads();              // all warps done before next grab
    }
}

// ---------------------------------------------------------------------------
// Kernel 3: per-batch softmax over S. One block per batch, 512 threads,
// 8 elems/thread. (Bias dropped: constant per row, cancels in softmax.)
// ---------------------------------------------------------------------------
__global__ __launch_bounds__(512) void k_softmax(float* __restrict__ out) {
    const int b   = blockIdx.x;
    const int tid = threadIdx.x;
    __shared__ float red[16];

    float e[8];
    float mx = -CUDART_INF_F;
#pragma unroll
    for (int i = 0; i < 8; ++i) {
        e[i] = g_energy[b * S + tid + i * 512];
        mx = fmaxf(mx, e[i]);
    }
#pragma unroll
    for (int off = 16; off > 0; off >>= 1)
        mx = fmaxf(mx, __shfl_xor_sync(0xFFFFFFFFu, mx, off));
    if ((tid & 31) == 0) red[tid >> 5] = mx;
    __syncthreads();
    if (tid < 32) {
        float m = (tid < 16) ? red[tid] : -CUDART_INF_F;
#pragma unroll
        for (int off = 8; off > 0; off >>= 1)
            m = fmaxf(m, __shfl_xor_sync(0xFFFFFFFFu, m, off));
        if (tid == 0) red[0] = m;
    }
    __syncthreads();
    mx = red[0];
    __syncthreads();

    float sum = 0.f;
#pragma unroll
    for (int i = 0; i < 8; ++i) {
        e[i] = __expf(e[i] - mx);
        sum += e[i];
    }
#pragma unroll
    for (int off = 16; off > 0; off >>= 1)
        sum += __shfl_xor_sync(0xFFFFFFFFu, sum, off);
    if ((tid & 31) == 0) red[tid >> 5] = sum;
    __syncthreads();
    if (tid < 32) {
        float s = (tid < 16) ? red[tid] : 0.f;
#pragma unroll
        for (int off = 8; off > 0; off >>= 1)
            s += __shfl_xor_sync(0xFFFFFFFFu, s, off);
        if (tid == 0) red[0] = s;
    }
    __syncthreads();
    const float inv = 1.0f / red[0];

#pragma unroll
    for (int i = 0; i < 8; ++i)
        out[b * S + tid + i * 512] = e[i] * inv;
}

// ---------------------------------------------------------------------------
extern "C" void kernel_launch(void* const* d_in, const int* in_sizes, int n_in,
                              void* d_out, int out_size) {
    const float* hidden = (const float*)d_in[0];   // [B,H]
    const float* enc    = (const float*)d_in[1];   // [B,S,2H]
    const float* W      = (const float*)d_in[2];   // [H,2H]
    // d_in[3] = bias: constant per row -> cancels in softmax, unused.
    float* out = (float*)d_out;                    // [B,1,S]

    k_reset<<<1, 1>>>();
    k_vpart<<<dim3(D / 128, B / 8, HS), 128>>>(hidden, W);
    k_vreduce<<<(B * D + 255) / 256, 256>>>();
    k_energy<<<NCTA_E, 512>>>(enc);
    k_softmax<<<B, 512>>>(out);
}

// round 6
// speedup vs baseline: 1.8764x; 1.8764x over previous
#include <cuda_runtime.h>
#include <cuda_bf16.h>
#include <math_constants.h>

// Shapes (fixed for this problem)
#define B  32
#define S  4096
#define H  1024
#define D  2048   // 2*H

#define HS 16           // h-splits for vpart
#define HC (H / HS)     // 64 h per split
#define BG 4            // batches per vpart CTA

// Scratch (device globals; no allocation allowed)
__device__ float g_vpart[HS][B * D];  // h-split partials of v = W^T hidden
__device__ float g_v[B * D];
__device__ float g_energy[B * S];

// ---------------------------------------------------------------------------
// Kernel 1: v_part[hs][b][d] = sum_{h in chunk hs} hidden[b][h] * W[h][d]
// grid (D/128, B/BG, HS) = 2048 CTAs, block 128. 64-iter loop, unroll 16
// (MLP ~16); W element reused across BG batches in registers.
// ---------------------------------------------------------------------------
__global__ __launch_bounds__(128) void k_vpart(const float* __restrict__ hidden,
                                               const float* __restrict__ W) {
    const int tid = threadIdx.x;
    const int d   = blockIdx.x * 128 + tid;
    const int bg  = blockIdx.y;           // batch group of BG
    const int hs  = blockIdx.z;           // h chunk of HC

    __shared__ float hsm[BG][HC];
    for (int idx = tid; idx < BG * HC; idx += 128) {
        int bl = idx / HC, hl = idx % HC;
        hsm[bl][hl] = hidden[(bg * BG + bl) * H + hs * HC + hl];
    }
    __syncthreads();

    float acc[BG];
#pragma unroll
    for (int j = 0; j < BG; ++j) acc[j] = 0.f;

    const float* Wp = W + (size_t)(hs * HC) * D + d;
#pragma unroll 16
    for (int hl = 0; hl < HC; ++hl) {
        float w = Wp[(size_t)hl * D];
#pragma unroll
        for (int j = 0; j < BG; ++j) acc[j] += hsm[j][hl] * w;
    }

#pragma unroll
    for (int j = 0; j < BG; ++j)
        g_vpart[hs][(bg * BG + j) * D + d] = acc[j];
}

// ---------------------------------------------------------------------------
// Kernel 1b: v = sum of HS partials (deterministic, no atomics)
// ---------------------------------------------------------------------------
__global__ void k_vreduce() {
    int idx = blockIdx.x * blockDim.x + threadIdx.x;   // B*D threads
    if (idx < B * D) {
        float s = 0.f;
#pragma unroll
        for (int p = 0; p < HS; ++p) s += g_vpart[p][idx];
        g_v[idx] = s;
    }
}

// ---------------------------------------------------------------------------
// Kernel 2: energies[b][s] = dot(enc[b][s][:], v[b][:])
// MULTI-WAVE (one 64-row tile per CTA): the HW work distributor keeps the
// SM's outstanding-load count saturated across CTA lifetimes — persistent
// variants with per-tile barriers measured 2x slower (5.3 TB/s, DRAM 67%).
// grid (S/64, B), block 512, 3 CTAs/SM. enc streamed with __ldcs.
// ---------------------------------------------------------------------------
__global__ __launch_bounds__(512, 3) void k_energy(const float* __restrict__ enc) {
    const int b    = blockIdx.y;
    const int tid  = threadIdx.x;
    const int warp = tid >> 5;
    const int lane = tid & 31;

    __shared__ float4 vsm[D / 4];   // 8KB

    vsm[tid] = reinterpret_cast<const float4*>(g_v + b * D)[tid];
    __syncthreads();

    const int s0 = blockIdx.x * 64 + warp * 4;

#pragma unroll
    for (int r = 0; r < 4; ++r) {
        const int s = s0 + r;
        const float4* e4 = reinterpret_cast<const float4*>(
            enc + ((size_t)b * S + s) * D);
        float acc = 0.f;
#pragma unroll
        for (int i = 0; i < 16; ++i) {
            float4 e = __ldcs(&e4[i * 32 + lane]);
            float4 v = vsm[i * 32 + lane];
            acc += e.x * v.x + e.y * v.y + e.z * v.z + e.w * v.w;
        }
#pragma unroll
        for (int off = 16; off > 0; off >>= 1)
            acc += __shfl_xor_sync(0xFFFFFFFFu, acc, off);
        if (lane == 0) g_energy[b * S + s] = acc;
    }
}

// ---------------------------------------------------------------------------
// Kernel 3: per-batch softmax over S. One block per batch, 512 threads,
// 8 elems/thread. (Bias dropped: constant per row, cancels in softmax.)
// ---------------------------------------------------------------------------
__global__ __launch_bounds__(512) void k_softmax(float* __restrict__ out) {
    const int b   = blockIdx.x;
    const int tid = threadIdx.x;
    __shared__ float red[16];

    float e[8];
    float mx = -CUDART_INF_F;
#pragma unroll
    for (int i = 0; i < 8; ++i) {
        e[i] = g_energy[b * S + tid + i * 512];
        mx = fmaxf(mx, e[i]);
    }
#pragma unroll
    for (int off = 16; off > 0; off >>= 1)
        mx = fmaxf(mx, __shfl_xor_sync(0xFFFFFFFFu, mx, off));
    if ((tid & 31) == 0) red[tid >> 5] = mx;
    __syncthreads();
    if (tid < 32) {
        float m = (tid < 16) ? red[tid] : -CUDART_INF_F;
#pragma unroll
        for (int off = 8; off > 0; off >>= 1)
            m = fmaxf(m, __shfl_xor_sync(0xFFFFFFFFu, m, off));
        if (tid == 0) red[0] = m;
    }
    __syncthreads();
    mx = red[0];
    __syncthreads();

    float sum = 0.f;
#pragma unroll
    for (int i = 0; i < 8; ++i) {
        e[i] = __expf(e[i] - mx);
        sum += e[i];
    }
#pragma unroll
    for (int off = 16; off > 0; off >>= 1)
        sum += __shfl_xor_sync(0xFFFFFFFFu, sum, off);
    if ((tid & 31) == 0) red[tid >> 5] = sum;
    __syncthreads();
    if (tid < 32) {
        float s = (tid < 16) ? red[tid] : 0.f;
#pragma unroll
        for (int off = 8; off > 0; off >>= 1)
            s += __shfl_xor_sync(0xFFFFFFFFu, s, off);
        if (tid == 0) red[0] = s;
    }
    __syncthreads();
    const float inv = 1.0f / red[0];

#pragma unroll
    for (int i = 0; i < 8; ++i)
        out[b * S + tid + i * 512] = e[i] * inv;
}

// ---------------------------------------------------------------------------
extern "C" void kernel_launch(void* const* d_in, const int* in_sizes, int n_in,
                              void* d_out, int out_size) {
    const float* hidden = (const float*)d_in[0];   // [B,H]
    const float* enc    = (const float*)d_in[1];   // [B,S,2H]
    const float* W      = (const float*)d_in[2];   // [H,2H]
    // d_in[3] = bias: constant per row -> cancels in softmax, unused.
    float* out = (float*)d_out;                    // [B,1,S]

    k_vpart<<<dim3(D / 128, B / BG, HS), 128>>>(hidden, W);
    k_vreduce<<<(B * D + 255) / 256, 256>>>();
    k_energy<<<dim3(S / 64, B), 512>>>(enc);
    k_softmax<<<B, 512>>>(out);
}

// round 7
// speedup vs baseline: 1.9536x; 1.0411x over previous
#include <cuda_runtime.h>
#include <cuda_bf16.h>
#include <math_constants.h>

// Shapes (fixed for this problem)
#define B  32
#define S  4096
#define H  1024
#define D  2048   // 2*H

#define HS 16           // h-splits for vpart
#define HC (H / HS)     // 64 h per split
#define BG 8            // batches per vpart CTA

// Scratch (device globals; no allocation allowed)
__device__ float g_vpart[HS][B * D];  // h-split partials of v = W^T hidden
__device__ float g_v[B * D];
__device__ float g_energy[B * S];

// ---------------------------------------------------------------------------
// Kernel 1: v_part[hs][b][d] = sum_{h in chunk hs} hidden[b][h] * W[h][d]
// grid (D/128, B/8, HS) = 1024 CTAs, block 128.
// hsm is TRANSPOSED ([hl][j]) so the 8 batch values come from 2 LDS.128
// instead of 8 scalar LDS -> 4x fewer smem wavefronts (old version was
// LDS-issue bound at ~8us).
// ---------------------------------------------------------------------------
__global__ __launch_bounds__(128) void k_vpart(const float* __restrict__ hidden,
                                               const float* __restrict__ W) {
    const int tid = threadIdx.x;
    const int d   = blockIdx.x * 128 + tid;
    const int bg  = blockIdx.y;           // batch group of 8
    const int hs  = blockIdx.z;           // h chunk of HC

    __shared__ float4 hsm4[HC][2];        // [hl][jj] : 8 batches as 2 float4
    for (int idx = tid; idx < BG * HC; idx += 128) {
        int j = idx & 7, hl = idx >> 3;
        reinterpret_cast<float*>(hsm4)[hl * 8 + j] =
            hidden[(bg * BG + j) * H + hs * HC + hl];
    }
    __syncthreads();

    float acc[8];
#pragma unroll
    for (int j = 0; j < 8; ++j) acc[j] = 0.f;

    const float* Wp = W + (size_t)(hs * HC) * D + d;
#pragma unroll 16
    for (int hl = 0; hl < HC; ++hl) {
        float w = Wp[(size_t)hl * D];
        float4 h0 = hsm4[hl][0];
        float4 h1 = hsm4[hl][1];
        acc[0] += h0.x * w;  acc[1] += h0.y * w;
        acc[2] += h0.z * w;  acc[3] += h0.w * w;
        acc[4] += h1.x * w;  acc[5] += h1.y * w;
        acc[6] += h1.z * w;  acc[7] += h1.w * w;
    }

#pragma unroll
    for (int j = 0; j < 8; ++j)
        g_vpart[hs][(bg * BG + j) * D + d] = acc[j];
}

// ---------------------------------------------------------------------------
// Kernel 1b: v = sum of HS partials (deterministic, no atomics)
// ---------------------------------------------------------------------------
__global__ void k_vreduce() {
    int idx = blockIdx.x * blockDim.x + threadIdx.x;   // B*D threads
    if (idx < B * D) {
        float s = 0.f;
#pragma unroll
        for (int p = 0; p < HS; ++p) s += g_vpart[p][idx];
        g_v[idx] = s;
    }
}

// ---------------------------------------------------------------------------
// Kernel 2: energies[b][s] = dot(enc[b][s][:], v[b][:])
// Multi-wave, one 64-row tile per CTA (HW distributor = scheduler; persistent
// variants measured 2x slower). Explicit e[16] register batch FORCES 16
// in-flight LDG.128 per warp (previous 40-reg build throttled MLP to ~8).
// grid (S/64, B), block 512, 3 CTAs/SM.
// ---------------------------------------------------------------------------
__global__ __launch_bounds__(512, 3) void k_energy(const float* __restrict__ enc) {
    const int b    = blockIdx.y;
    const int tid  = threadIdx.x;
    const int warp = tid >> 5;
    const int lane = tid & 31;

    __shared__ float4 vsm[D / 4];   // 8KB

    vsm[tid] = reinterpret_cast<const float4*>(g_v + b * D)[tid];
    __syncthreads();

    const int s0 = blockIdx.x * 64 + warp * 4;

#pragma unroll
    for (int r = 0; r < 4; ++r) {
        const int s = s0 + r;
        const float4* e4 = reinterpret_cast<const float4*>(
            enc + ((size_t)b * S + s) * D);

        float4 e[16];
#pragma unroll
        for (int i = 0; i < 16; ++i) e[i] = __ldcs(&e4[i * 32 + lane]);

        float a0 = 0.f, a1 = 0.f;
#pragma unroll
        for (int i = 0; i < 16; i += 2) {
            float4 v0 = vsm[i * 32 + lane];
            float4 v1 = vsm[(i + 1) * 32 + lane];
            a0 += e[i].x * v0.x + e[i].y * v0.y + e[i].z * v0.z + e[i].w * v0.w;
            a1 += e[i+1].x * v1.x + e[i+1].y * v1.y + e[i+1].z * v1.z + e[i+1].w * v1.w;
        }
        float acc = a0 + a1;
#pragma unroll
        for (int off = 16; off > 0; off >>= 1)
            acc += __shfl_xor_sync(0xFFFFFFFFu, acc, off);
        if (lane == 0) g_energy[b * S + s] = acc;
    }
}

// ---------------------------------------------------------------------------
// Kernel 3: per-batch ONLINE softmax over S (single (m,s)-pair reduction
// round instead of separate max and sum rounds). One block per batch,
// 512 threads, 8 elems/thread. Bias dropped (cancels in softmax).
// ---------------------------------------------------------------------------
__global__ __launch_bounds__(512) void k_softmax(float* __restrict__ out) {
    const int b   = blockIdx.x;
    const int tid = threadIdx.x;
    __shared__ float red_m[16], red_s[16];

    float e[8];
    float m = -CUDART_INF_F;
#pragma unroll
    for (int i = 0; i < 8; ++i) {
        e[i] = g_energy[b * S + tid + i * 512];
        m = fmaxf(m, e[i]);
    }
    float s = 0.f;
#pragma unroll
    for (int i = 0; i < 8; ++i) s += __expf(e[i] - m);

    // warp-level (m,s) merge
#pragma unroll
    for (int off = 16; off > 0; off >>= 1) {
        float mo = __shfl_xor_sync(0xFFFFFFFFu, m, off);
        float so = __shfl_xor_sync(0xFFFFFFFFu, s, off);
        float M  = fmaxf(m, mo);
        s = s * __expf(m - M) + so * __expf(mo - M);
        m = M;
    }
    if ((tid & 31) == 0) { red_m[tid >> 5] = m; red_s[tid >> 5] = s; }
    __syncthreads();
    if (tid < 32) {
        float mm = (tid < 16) ? red_m[tid] : -CUDART_INF_F;
        float ss = (tid < 16) ? red_s[tid] : 0.f;
#pragma unroll
        for (int off = 8; off > 0; off >>= 1) {
            float mo = __shfl_xor_sync(0xFFFFFFFFu, mm, off);
            float so = __shfl_xor_sync(0xFFFFFFFFu, ss, off);
            float M  = fmaxf(mm, mo);
            ss = ss * __expf(mm - M) + so * __expf(mo - M);
            mm = M;
        }
        if (tid == 0) { red_m[0] = mm; red_s[0] = ss; }
    }
    __syncthreads();
    const float M   = red_m[0];
    const float inv = 1.0f / red_s[0];

#pragma unroll
    for (int i = 0; i < 8; ++i)
        out[b * S + tid + i * 512] = __expf(e[i] - M) * inv;
}

// ---------------------------------------------------------------------------
extern "C" void kernel_launch(void* const* d_in, const int* in_sizes, int n_in,
                              void* d_out, int out_size) {
    const float* hidden = (const float*)d_in[0];   // [B,H]
    const float* enc    = (const float*)d_in[1];   // [B,S,2H]
    const float* W      = (const float*)d_in[2];   // [H,2H]
    // d_in[3] = bias: constant per row -> cancels in softmax, unused.
    float* out = (float*)d_out;                    // [B,1,S]

    k_vpart<<<dim3(D / 128, B / BG, HS), 128>>>(hidden, W);
    k_vreduce<<<(B * D + 255) / 256, 256>>>();
    k_energy<<<dim3(S / 64, B), 512>>>(enc);
    k_softmax<<<B, 512>>>(out);
}

// round 8
// speedup vs baseline: 2.0260x; 1.0370x over previous
#include <cuda_runtime.h>
#include <cuda_bf16.h>
#include <math_constants.h>

// Shapes (fixed for this problem)
#define B  32
#define S  4096
#define H  1024
#define D  2048   // 2*H

#define HS 16           // h-splits for vpart
#define HC (H / HS)     // 64 h per split
#define BG 8            // batches per vpart CTA

// Scratch (device globals; no allocation allowed)
__device__ float g_vpart[HS][B * D];  // h-split partials of v = W^T hidden
__device__ float g_v[B * D];
__device__ float g_energy[B * S];

// ---------------------------------------------------------------------------
// Kernel 1: v_part[hs][b][d] = sum_{h in chunk hs} hidden[b][h] * W[h][d]
// grid (D/128, B/8, HS) = 1024 CTAs, block 128.
// hsm TRANSPOSED ([hl][j]): 8 batch values per iter come from 2 LDS.128
// instead of 8 scalar LDS (old version was LDS-wavefront bound).
// ---------------------------------------------------------------------------
__global__ __launch_bounds__(128) void k_vpart(const float* __restrict__ hidden,
                                               const float* __restrict__ W) {
    const int tid = threadIdx.x;
    const int d   = blockIdx.x * 128 + tid;
    const int bg  = blockIdx.y;           // batch group of 8
    const int hs  = blockIdx.z;           // h chunk of HC

    __shared__ float4 hsm4[HC][2];        // [hl][jj] : 8 batches as 2 float4
    for (int idx = tid; idx < BG * HC; idx += 128) {
        int j = idx & 7, hl = idx >> 3;
        reinterpret_cast<float*>(hsm4)[hl * 8 + j] =
            hidden[(bg * BG + j) * H + hs * HC + hl];
    }
    __syncthreads();

    float acc[8];
#pragma unroll
    for (int j = 0; j < 8; ++j) acc[j] = 0.f;

    const float* Wp = W + (size_t)(hs * HC) * D + d;
#pragma unroll 16
    for (int hl = 0; hl < HC; ++hl) {
        float w = Wp[(size_t)hl * D];
        float4 h0 = hsm4[hl][0];
        float4 h1 = hsm4[hl][1];
        acc[0] += h0.x * w;  acc[1] += h0.y * w;
        acc[2] += h0.z * w;  acc[3] += h0.w * w;
        acc[4] += h1.x * w;  acc[5] += h1.y * w;
        acc[6] += h1.z * w;  acc[7] += h1.w * w;
    }

#pragma unroll
    for (int j = 0; j < 8; ++j)
        g_vpart[hs][(bg * BG + j) * D + d] = acc[j];
}

// ---------------------------------------------------------------------------
// Kernel 1b: v = sum of HS partials, float4-vectorized (deterministic)
// ---------------------------------------------------------------------------
__global__ void k_vreduce() {
    int idx = blockIdx.x * blockDim.x + threadIdx.x;   // B*D/4 threads
    if (idx < B * D / 4) {
        float4 s = make_float4(0.f, 0.f, 0.f, 0.f);
#pragma unroll
        for (int p = 0; p < HS; ++p) {
            float4 a = reinterpret_cast<const float4*>(g_vpart[p])[idx];
            s.x += a.x; s.y += a.y; s.z += a.z; s.w += a.w;
        }
        reinterpret_cast<float4*>(g_v)[idx] = s;
    }
}

// ---------------------------------------------------------------------------
// Kernel 2: energies[b][s] = dot(enc[b][s][:], v[b][:])
// Multi-wave, one 64-row tile per CTA, compiler-scheduled loads (the
// explicit e[16] batch spilled to local under the 42-reg occupancy cap
// of launch_bounds(512,3) — reverted to the best-measured round-3 loop).
// grid (S/64, B), block 512, 3 CTAs/SM. enc streamed with __ldcs.
// ---------------------------------------------------------------------------
__global__ __launch_bounds__(512, 3) void k_energy(const float* __restrict__ enc) {
    const int b    = blockIdx.y;
    const int tid  = threadIdx.x;
    const int warp = tid >> 5;
    const int lane = tid & 31;

    __shared__ float4 vsm[D / 4];   // 8KB

    vsm[tid] = reinterpret_cast<const float4*>(g_v + b * D)[tid];
    __syncthreads();

    const int s0 = blockIdx.x * 64 + warp * 4;

#pragma unroll
    for (int r = 0; r < 4; ++r) {
        const int s = s0 + r;
        const float4* e4 = reinterpret_cast<const float4*>(
            enc + ((size_t)b * S + s) * D);
        float acc = 0.f;
#pragma unroll
        for (int i = 0; i < 16; ++i) {
            float4 e = __ldcs(&e4[i * 32 + lane]);
            float4 v = vsm[i * 32 + lane];
            acc += e.x * v.x + e.y * v.y + e.z * v.z + e.w * v.w;
        }
#pragma unroll
        for (int off = 16; off > 0; off >>= 1)
            acc += __shfl_xor_sync(0xFFFFFFFFu, acc, off);
        if (lane == 0) g_energy[b * S + s] = acc;
    }
}

// ---------------------------------------------------------------------------
// Kernel 3: per-batch ONLINE softmax over S (single (m,s) reduction round).
// One block per batch, 512 threads, 8 elems/thread. Bias dropped
// (constant per row, cancels in softmax).
// ---------------------------------------------------------------------------
__global__ __launch_bounds__(512) void k_softmax(float* __restrict__ out) {
    const int b   = blockIdx.x;
    const int tid = threadIdx.x;
    __shared__ float red_m[16], red_s[16];

    float e[8];
    float m = -CUDART_INF_F;
#pragma unroll
    for (int i = 0; i < 8; ++i) {
        e[i] = g_energy[b * S + tid + i * 512];
        m = fmaxf(m, e[i]);
    }
    float s = 0.f;
#pragma unroll
    for (int i = 0; i < 8; ++i) s += __expf(e[i] - m);

#pragma unroll
    for (int off = 16; off > 0; off >>= 1) {
        float mo = __shfl_xor_sync(0xFFFFFFFFu, m, off);
        float so = __shfl_xor_sync(0xFFFFFFFFu, s, off);
        float M  = fmaxf(m, mo);
        s = s * __expf(m - M) + so * __expf(mo - M);
        m = M;
    }
    if ((tid & 31) == 0) { red_m[tid >> 5] = m; red_s[tid >> 5] = s; }
    __syncthreads();
    if (tid < 32) {
        float mm = (tid < 16) ? red_m[tid] : -CUDART_INF_F;
        float ss = (tid < 16) ? red_s[tid] : 0.f;
#pragma unroll
        for (int off = 8; off > 0; off >>= 1) {
            float mo = __shfl_xor_sync(0xFFFFFFFFu, mm, off);
            float so = __shfl_xor_sync(0xFFFFFFFFu, ss, off);
            float M  = fmaxf(mm, mo);
            ss = ss * __expf(mm - M) + so * __expf(mo - M);
            mm = M;
        }
        if (tid == 0) { red_m[0] = mm; red_s[0] = ss; }
    }
    __syncthreads();
    const float M   = red_m[0];
    const float inv = 1.0f / red_s[0];

#pragma unroll
    for (int i = 0; i < 8; ++i)
        out[b * S + tid + i * 512] = __expf(e[i] - M) * inv;
}

// ---------------------------------------------------------------------------
extern "C" void kernel_launch(void* const* d_in, const int* in_sizes, int n_in,
                              void* d_out, int out_size) {
    const float* hidden = (const float*)d_in[0];   // [B,H]
    const float* enc    = (const float*)d_in[1];   // [B,S,2H]
    const float* W      = (const float*)d_in[2];   // [H,2H]
    // d_in[3] = bias: constant per row -> cancels in softmax, unused.
    float* out = (float*)d_out;                    // [B,1,S]

    k_vpart<<<dim3(D / 128, B / BG, HS), 128>>>(hidden, W);
    k_vreduce<<<(B * D / 4 + 255) / 256, 256>>>();
    k_energy<<<dim3(S / 64, B), 512>>>(enc);
    k_softmax<<<B, 512>>>(out);
}